// round 9
// baseline (speedup 1.0000x reference)
#include <cuda_runtime.h>
#include <cuda_bf16.h>
#include <cstdint>

// Problem constants
#define BB 1024
#define RR 8
#define CC 1024
#define DD 16384
#define KK 32
#define NCAND 40
#define SST 40          // smem row stride in bf16 (80B: 16B aligned, LDSM conflict-free)
#define NSTG 4          // cp.async pipeline depth
#define STG_ELEMS (128 * SST)                  // bf16 elems per operand-stage
#define GEMM_SMEM (NSTG * 2 * STG_ELEMS * 2)   // 81920 bytes

// ---------------- device scratch (allocation-free rule: __device__ globals) ----
__device__ __nv_bfloat16 g_h  [(size_t)BB * RR * DD];        // 256 MB approx h (bf16)
__device__ float         g_xc [(size_t)BB * RR * CC];        // 32 MB  x - decoder_b (fp32)
__device__ __nv_bfloat16 g_Ah [(size_t)RR * BB * CC];        // 16 MB  bf16 acts [r][b][c]
__device__ __nv_bfloat16 g_Bh [(size_t)RR * DD * CC];        // 256 MB bf16 weights [r][d][c]
__device__ float         g_dwT[(size_t)RR * DD * CC];        // 512 MB decoder_w transposed
__device__ int           g_cand[(size_t)BB * RR * NCAND];
__device__ float         g_vals[(size_t)BB * RR * KK];
__device__ int           g_idx [(size_t)BB * RR * KK];

// ---------------- prep ----------------------------------------------------------
__global__ void prep_x_kernel(const float* __restrict__ x,
                              const float* __restrict__ db) {
    int idx = blockIdx.x * blockDim.x + threadIdx.x;
    int b = idx >> 13;
    int r = (idx >> 10) & 7;
    int c = idx & 1023;
    float xc = x[idx] - db[r * CC + c];
    g_xc[idx] = xc;
    g_Ah[((size_t)r * BB + b) * CC + c] = __float2bfloat16(xc);
}

__global__ void prep_w_kernel(const float* __restrict__ ew) {
    int idx = blockIdx.x * blockDim.x + threadIdx.x;
    g_Bh[idx] = __float2bfloat16(ew[idx]);
}

__global__ void transpose_dw_kernel(const float* __restrict__ dw) {
    __shared__ float tile[32][33];
    int d0 = blockIdx.x * 32;
    int c0 = blockIdx.y * 32;
    int r  = blockIdx.z;
    int tx = threadIdx.x, ty = threadIdx.y;
    #pragma unroll
    for (int j = 0; j < 4; j++) {
        int c = c0 + ty + j * 8;
        tile[ty + j * 8][tx] = dw[((size_t)r * CC + c) * DD + d0 + tx];
    }
    __syncthreads();
    #pragma unroll
    for (int j = 0; j < 4; j++) {
        int d = d0 + ty + j * 8;
        g_dwT[((size_t)r * DD + d) * CC + c0 + tx] = tile[tx][ty + j * 8];
    }
}

// ---------------- encoder GEMM: bf16 mma m16n8k16, 4-stage cp.async + ldmatrix --
// Block 128x128, 8 warps (2x4), warp tile 64x32.

__device__ __forceinline__ void mma16816(float* c, const uint32_t* a,
                                         uint32_t b0, uint32_t b1) {
    asm volatile(
        "mma.sync.aligned.m16n8k16.row.col.f32.bf16.bf16.f32 "
        "{%0,%1,%2,%3}, {%4,%5,%6,%7}, {%8,%9}, {%0,%1,%2,%3};\n"
        : "+f"(c[0]), "+f"(c[1]), "+f"(c[2]), "+f"(c[3])
        : "r"(a[0]), "r"(a[1]), "r"(a[2]), "r"(a[3]), "r"(b0), "r"(b1));
}

__device__ __forceinline__ void ldsm4(uint32_t* d, uint32_t addr) {
    asm volatile("ldmatrix.sync.aligned.m8n8.x4.shared.b16 {%0,%1,%2,%3}, [%4];"
                 : "=r"(d[0]), "=r"(d[1]), "=r"(d[2]), "=r"(d[3]) : "r"(addr));
}

__device__ __forceinline__ void cp16(uint32_t dst, const void* src) {
    asm volatile("cp.async.cg.shared.global [%0], [%1], 16;\n"
                 :: "r"(dst), "l"(src) : "memory");
}

__global__ __launch_bounds__(256, 2)
void encoder_gemm_kernel(const __nv_bfloat16* __restrict__ Ap,
                         const __nv_bfloat16* __restrict__ Bp,
                         const float* __restrict__ eb,
                         __nv_bfloat16* __restrict__ H) {
    extern __shared__ __nv_bfloat16 smem[];   // [NSTG][A|B][128*SST]
    const int mt = blockIdx.x;        // 8  (fastest: B-tile L2 reuse)
    const int nt = blockIdx.y;        // 128
    const int r  = blockIdx.z;        // 8
    const int tid = threadIdx.x;
    const int wid = tid >> 5, lane = tid & 31;
    const int wm = wid >> 2, wn = wid & 3;    // 2x4 warps, 64x32 per warp
    const int g = lane >> 2, t = lane & 3;

    float acc[4][4][4];
    #pragma unroll
    for (int i = 0; i < 4; i++)
        #pragma unroll
        for (int j = 0; j < 4; j++)
            #pragma unroll
            for (int q = 0; q < 4; q++) acc[i][j][q] = 0.f;

    const uint32_t s0 = (uint32_t)__cvta_generic_to_shared(smem);

    const int row0 = tid >> 2, seg0 = (tid & 3) * 8;
    const int row1 = (tid + 256) >> 2, seg1 = ((tid + 256) & 3) * 8;
    const size_t aG0 = ((size_t)r * BB + (size_t)mt * 128 + row0) * CC + seg0;
    const size_t aG1 = ((size_t)r * BB + (size_t)mt * 128 + row1) * CC + seg1;
    const size_t bG0 = ((size_t)r * DD + (size_t)nt * 128 + row0) * CC + seg0;
    const size_t bG1 = ((size_t)r * DD + (size_t)nt * 128 + row1) * CC + seg1;
    const uint32_t d0b = (uint32_t)(row0 * SST + seg0) * 2;
    const uint32_t d1b = (uint32_t)(row1 * SST + seg1) * 2;

    auto prefetch = [&](int kt) {
        int stg = kt % NSTG;
        uint32_t aBase = s0 + stg * (2 * STG_ELEMS * 2);
        uint32_t bBase = aBase + STG_ELEMS * 2;
        size_t ko = (size_t)kt * 32;
        cp16(aBase + d0b, Ap + aG0 + ko);
        cp16(aBase + d1b, Ap + aG1 + ko);
        cp16(bBase + d0b, Bp + bG0 + ko);
        cp16(bBase + d1b, Bp + bG1 + ko);
    };

    const uint32_t fRow = lane & 15;
    const uint32_t fK   = (lane >> 4) * 8;
    const uint32_t aF = ((wm * 64 + fRow) * SST + fK) * 2;
    const uint32_t bF = ((wn * 32 + fRow) * SST + fK) * 2;

    #pragma unroll
    for (int p = 0; p < NSTG - 1; p++) {
        prefetch(p);
        asm volatile("cp.async.commit_group;" ::: "memory");
    }

    const int NKT = CC / 32;   // 32
    for (int kt = 0; kt < NKT; kt++) {
        asm volatile("cp.async.wait_group %0;" :: "n"(NSTG - 2) : "memory"); // group kt done
        __syncthreads();        // all warps past compute(kt-1); stage (kt-1)%NSTG reusable
        if (kt + NSTG - 1 < NKT) prefetch(kt + NSTG - 1);
        asm volatile("cp.async.commit_group;" ::: "memory");

        int stg = kt % NSTG;
        const uint32_t baseA = s0 + stg * (2 * STG_ELEMS * 2) + aF;
        const uint32_t baseB = s0 + stg * (2 * STG_ELEMS * 2) + STG_ELEMS * 2 + bF;
        #pragma unroll
        for (int ks = 0; ks < 2; ks++) {
            const int ko = ks * 16;
            uint32_t afr[4][4], bq[2][4];
            #pragma unroll
            for (int mi = 0; mi < 4; mi++) ldsm4(afr[mi], baseA + (mi * 16 * SST + ko) * 2);
            #pragma unroll
            for (int nb = 0; nb < 2; nb++) ldsm4(bq[nb], baseB + (nb * 16 * SST + ko) * 2);
            #pragma unroll
            for (int mi = 0; mi < 4; mi++)
                #pragma unroll
                for (int nb = 0; nb < 2; nb++) {
                    mma16816(acc[mi][2 * nb],     afr[mi], bq[nb][0], bq[nb][2]);
                    mma16816(acc[mi][2 * nb + 1], afr[mi], bq[nb][1], bq[nb][3]);
                }
        }
    }

    // epilogue: h = acc + encoder_b -> bf16
    const size_t ebBase = (size_t)r * DD;
    #pragma unroll
    for (int mi = 0; mi < 4; mi++) {
        int b0 = mt * 128 + wm * 64 + mi * 16 + g;
        #pragma unroll
        for (int ni = 0; ni < 4; ni++) {
            int dd0 = nt * 128 + wn * 32 + ni * 8 + 2 * t;
            float e0 = eb[ebBase + dd0];
            float e1 = eb[ebBase + dd0 + 1];
            __nv_bfloat162 v0, v1;
            v0.x = __float2bfloat16(acc[mi][ni][0] + e0);
            v0.y = __float2bfloat16(acc[mi][ni][1] + e1);
            v1.x = __float2bfloat16(acc[mi][ni][2] + e0);
            v1.y = __float2bfloat16(acc[mi][ni][3] + e1);
            *(__nv_bfloat162*)&H[((size_t)b0 * RR + r) * DD + dd0]       = v0;
            *(__nv_bfloat162*)&H[((size_t)(b0 + 8) * RR + r) * DD + dd0] = v1;
        }
    }
}

// ---------------- approx top-NCAND: bisection on register-resident u16 keys -----
__global__ __launch_bounds__(256)
void topk_kernel(const __nv_bfloat16* __restrict__ H) {
    __shared__ int s_warp[8];
    __shared__ int s_total;
    __shared__ int s_cnt, s_tiecnt;
    __shared__ int out_idx[NCAND];
    __shared__ int tie_idx[128];

    const int row = blockIdx.x;               // b*R + r
    const int tid = threadIdx.x;              // 256 threads
    const int wid = tid >> 5, lane = tid & 31;
    const uint4* h4 = (const uint4*)(H + (size_t)row * DD);

    // load 64 bf16 per thread; convert to sortable u16, packed 2-per-u32
    uint32_t kreg[32];
    #pragma unroll
    for (int c = 0; c < 8; c++) {
        uint4 v = h4[tid + c * 256];
        uint32_t w[4] = {v.x, v.y, v.z, v.w};
        #pragma unroll
        for (int q = 0; q < 4; q++) {
            uint32_t x = w[q];
            uint32_t neg = (x >> 15) & 0x00010001u;
            kreg[c * 4 + q] = x ^ (0x80008000u | (neg * 0x7FFFu));
        }
    }

    // bisection: smallest T with #{k > T} < NCAND
    int lo = -1, hi = 65535;
    for (int it = 0; it < 16; it++) {
        int mid = (lo + hi) >> 1;
        uint32_t m2 = (uint32_t)mid * 0x00010001u;
        uint32_t accv = 0;
        #pragma unroll
        for (int i = 0; i < 32; i++) accv += __vsetgtu2(kreg[i], m2);
        int cnt = (int)((accv & 0xFFFF) + (accv >> 16));
        #pragma unroll
        for (int o = 16; o > 0; o >>= 1) cnt += __shfl_xor_sync(0xFFFFFFFFu, cnt, o);
        if (lane == 0) s_warp[wid] = cnt;
        __syncthreads();
        if (tid == 0) {
            int tot = 0;
            #pragma unroll
            for (int w = 0; w < 8; w++) tot += s_warp[w];
            s_total = tot;
        }
        __syncthreads();
        if (s_total < NCAND) hi = mid; else lo = mid;
        __syncthreads();
    }
    const uint32_t T = (uint32_t)hi;

    if (tid == 0) { s_cnt = 0; s_tiecnt = 0; }
    __syncthreads();

    // collect: > T -> out list (< NCAND of them); == T -> tie list
    #pragma unroll
    for (int c = 0; c < 8; c++) {
        int ibase = (tid + c * 256) * 8;
        #pragma unroll
        for (int q = 0; q < 4; q++) {
            uint32_t k2 = kreg[c * 4 + q];
            uint32_t klo = k2 & 0xFFFF, khi = k2 >> 16;
            if (klo > T)       { int p = atomicAdd(&s_cnt, 1);    out_idx[p] = ibase + 2 * q; }
            else if (klo == T) { int p = atomicAdd(&s_tiecnt, 1); if (p < 128) tie_idx[p] = ibase + 2 * q; }
            if (khi > T)       { int p = atomicAdd(&s_cnt, 1);    out_idx[p] = ibase + 2 * q + 1; }
            else if (khi == T) { int p = atomicAdd(&s_tiecnt, 1); if (p < 128) tie_idx[p] = ibase + 2 * q + 1; }
        }
    }
    __syncthreads();
    if (tid == 0) {
        int gcnt = s_cnt;
        int need = NCAND - gcnt;   // >= 1, <= min(tiecnt,128) candidates available
        for (int a = 0; a < need; a++) out_idx[gcnt + a] = tie_idx[a];
    }
    __syncthreads();
    if (tid < NCAND) g_cand[(size_t)row * NCAND + tid] = out_idx[tid];
}

// ---------------- exact fp32 refine of NCAND candidates -> top-32 ---------------
__global__ __launch_bounds__(256)
void refine_kernel(const float* __restrict__ ew, const float* __restrict__ eb) {
    __shared__ float sxc[CC];
    __shared__ float sval[NCAND];
    __shared__ int   scand[NCAND];

    const int row = blockIdx.x;
    const int r   = row & 7;
    const int tid = threadIdx.x;
    const int wid = tid >> 5, lane = tid & 31;

    for (int i = tid; i < CC; i += 256) sxc[i] = g_xc[(size_t)row * CC + i];
    if (tid < NCAND) scand[tid] = g_cand[(size_t)row * NCAND + tid];
    __syncthreads();

    const float4* xs4 = (const float4*)sxc;
    #pragma unroll
    for (int j = 0; j < NCAND / 8; j++) {
        int ci = j * 8 + wid;                 // 5 rounds x 8 warps = 40
        int d = scand[ci];
        const float4* wr = (const float4*)(ew + ((size_t)r * DD + d) * CC);
        float acc = 0.f;
        #pragma unroll
        for (int it = 0; it < 8; it++) {
            float4 a = xs4[it * 32 + lane];
            float4 b = wr[it * 32 + lane];
            acc += a.x * b.x;
            acc += a.y * b.y;
            acc += a.z * b.z;
            acc += a.w * b.w;
        }
        #pragma unroll
        for (int o = 16; o > 0; o >>= 1)
            acc += __shfl_xor_sync(0xFFFFFFFFu, acc, o);
        if (lane == 0) sval[ci] = acc + eb[(size_t)r * DD + d];
    }
    __syncthreads();

    if (tid < NCAND) {
        float v = sval[tid];
        int   d = scand[tid];
        int rank = 0;
        #pragma unroll
        for (int j = 0; j < NCAND; j++) {
            float vj = sval[j];
            int   dj = scand[j];
            rank += (vj > v) || (vj == v && dj < d);
        }
        if (rank < KK) {
            g_idx [(size_t)row * KK + rank] = d;
            g_vals[(size_t)row * KK + rank] = v > 0.f ? v : 0.f;
        }
    }
}

// ---------------- sparse decode --------------------------------------------------
__global__ __launch_bounds__(256)
void decode_kernel(const float* __restrict__ db, float* __restrict__ out) {
    __shared__ float sval[KK];
    __shared__ int   sidx[KK];
    const int b = blockIdx.x;
    const int r = blockIdx.y;
    const int tid = threadIdx.x;
    const size_t row = (size_t)b * RR + r;
    if (tid < KK) {
        sval[tid] = g_vals[row * KK + tid];
        sidx[tid] = g_idx [row * KK + tid];
    }
    __syncthreads();
    const float* dwr = g_dwT + (size_t)r * DD * CC;
    #pragma unroll
    for (int it = 0; it < 4; it++) {
        int c = tid + it * 256;
        float acc = db[r * CC + c];
        #pragma unroll
        for (int j = 0; j < KK; j++)
            acc += sval[j] * dwr[(size_t)sidx[j] * CC + c];
        out[row * CC + c] = acc;
    }
}

// ---------------- launch ----------------------------------------------------------
extern "C" void kernel_launch(void* const* d_in, const int* in_sizes, int n_in,
                              void* d_out, int out_size) {
    const float* x  = (const float*)d_in[0];
    const float* ew = (const float*)d_in[1];
    const float* eb = (const float*)d_in[2];
    const float* dw = (const float*)d_in[3];
    const float* db = (const float*)d_in[4];
    float* out = (float*)d_out;

    __nv_bfloat16* h_ptr;  cudaGetSymbolAddress((void**)&h_ptr, g_h);
    __nv_bfloat16* a_ptr;  cudaGetSymbolAddress((void**)&a_ptr, g_Ah);
    __nv_bfloat16* b_ptr;  cudaGetSymbolAddress((void**)&b_ptr, g_Bh);

    cudaFuncSetAttribute(encoder_gemm_kernel,
                         cudaFuncAttributeMaxDynamicSharedMemorySize, GEMM_SMEM);

    prep_x_kernel<<<(BB * RR * CC) / 256, 256>>>(x, db);
    prep_w_kernel<<<(RR * DD * CC) / 256, 256>>>(ew);
    transpose_dw_kernel<<<dim3(DD / 32, CC / 32, RR), dim3(32, 8)>>>(dw);
    encoder_gemm_kernel<<<dim3(BB / 128, DD / 128, RR), 256, GEMM_SMEM>>>(a_ptr, b_ptr, eb, h_ptr);
    topk_kernel<<<BB * RR, 256>>>(h_ptr);
    refine_kernel<<<BB * RR, 256>>>(ew, eb);
    decode_kernel<<<dim3(BB, RR), 256>>>(db, out);
}

// round 11
// speedup vs baseline: 1.0139x; 1.0139x over previous
#include <cuda_runtime.h>
#include <cuda_bf16.h>
#include <cuda_fp8.h>
#include <cstdint>

// Problem constants
#define BB 1024
#define RR 8
#define CC 1024
#define DD 16384
#define KK 32
#define NCAND 96
#define SSTB 80         // smem row stride in BYTES (16B-aligned, LDSM conflict-free)
#define NSTG 4          // cp.async pipeline depth
#define STG_BYTES (128 * SSTB)                 // bytes per operand-stage (10240)
#define GEMM_SMEM (NSTG * 2 * STG_BYTES)       // 81920 bytes

// ---------------- device scratch (allocation-free rule: __device__ globals) ----
__device__ __nv_bfloat16 g_h  [(size_t)BB * RR * DD];        // 256 MB approx h (bf16)
__device__ float         g_xc [(size_t)BB * RR * CC];        // 32 MB  x - decoder_b (fp32)
__device__ uint8_t       g_A8 [(size_t)RR * BB * CC];        // 8 MB   e4m3 acts [r][b][c]
__device__ uint8_t       g_B8 [(size_t)RR * DD * CC];        // 128 MB e4m3 weights [r][d][c]
__device__ float         g_dwT[(size_t)RR * DD * CC];        // 512 MB decoder_w transposed
__device__ int           g_cand[(size_t)BB * RR * NCAND];
__device__ float         g_vals[(size_t)BB * RR * KK];
__device__ int           g_idx [(size_t)BB * RR * KK];

// ---------------- prep ----------------------------------------------------------
__global__ void prep_x_kernel(const float* __restrict__ x,
                              const float* __restrict__ db) {
    int idx = blockIdx.x * blockDim.x + threadIdx.x;
    int b = idx >> 13;
    int r = (idx >> 10) & 7;
    int c = idx & 1023;
    float xc = x[idx] - db[r * CC + c];
    g_xc[idx] = xc;
    g_A8[((size_t)r * BB + b) * CC + c] =
        (uint8_t)__nv_cvt_float_to_fp8(xc, __NV_SATFINITE, __NV_E4M3);
}

__global__ void prep_w_kernel(const float* __restrict__ ew) {
    int idx = blockIdx.x * blockDim.x + threadIdx.x;
    g_B8[idx] = (uint8_t)__nv_cvt_float_to_fp8(ew[idx], __NV_SATFINITE, __NV_E4M3);
}

__global__ void transpose_dw_kernel(const float* __restrict__ dw) {
    __shared__ float tile[32][33];
    int d0 = blockIdx.x * 32;
    int c0 = blockIdx.y * 32;
    int r  = blockIdx.z;
    int tx = threadIdx.x, ty = threadIdx.y;
    #pragma unroll
    for (int j = 0; j < 4; j++) {
        int c = c0 + ty + j * 8;
        tile[ty + j * 8][tx] = dw[((size_t)r * CC + c) * DD + d0 + tx];
    }
    __syncthreads();
    #pragma unroll
    for (int j = 0; j < 4; j++) {
        int d = d0 + ty + j * 8;
        g_dwT[((size_t)r * DD + d) * CC + c0 + tx] = tile[tx][ty + j * 8];
    }
}

// ---------------- encoder GEMM: e4m3 mma m16n8k32, 4-stage cp.async + ldmatrix --
// Block 128x128, 8 warps (2x4), warp tile 64x32. K-chunk per iter = 64 fp8.

__device__ __forceinline__ void mma_fp8(float* c, const uint32_t* a,
                                        uint32_t b0, uint32_t b1) {
    asm volatile(
        "mma.sync.aligned.m16n8k32.row.col.f32.e4m3.e4m3.f32 "
        "{%0,%1,%2,%3}, {%4,%5,%6,%7}, {%8,%9}, {%0,%1,%2,%3};\n"
        : "+f"(c[0]), "+f"(c[1]), "+f"(c[2]), "+f"(c[3])
        : "r"(a[0]), "r"(a[1]), "r"(a[2]), "r"(a[3]), "r"(b0), "r"(b1));
}

__device__ __forceinline__ void ldsm4(uint32_t* d, uint32_t addr) {
    asm volatile("ldmatrix.sync.aligned.m8n8.x4.shared.b16 {%0,%1,%2,%3}, [%4];"
                 : "=r"(d[0]), "=r"(d[1]), "=r"(d[2]), "=r"(d[3]) : "r"(addr));
}

__device__ __forceinline__ void cp16(uint32_t dst, const void* src) {
    asm volatile("cp.async.cg.shared.global [%0], [%1], 16;\n"
                 :: "r"(dst), "l"(src) : "memory");
}

__global__ __launch_bounds__(256, 2)
void encoder_gemm_kernel(const uint8_t* __restrict__ Ap,
                         const uint8_t* __restrict__ Bp,
                         const float* __restrict__ eb,
                         __nv_bfloat16* __restrict__ H) {
    extern __shared__ uint8_t smem[];   // [NSTG][A|B][128*SSTB]
    const int mt = blockIdx.x;        // 8  (fastest: B-tile L2 reuse)
    const int nt = blockIdx.y;        // 128
    const int r  = blockIdx.z;        // 8
    const int tid = threadIdx.x;
    const int wid = tid >> 5, lane = tid & 31;
    const int wm = wid >> 2, wn = wid & 3;    // 2x4 warps, 64x32 per warp
    const int g = lane >> 2, t = lane & 3;

    float acc[4][4][4];
    #pragma unroll
    for (int i = 0; i < 4; i++)
        #pragma unroll
        for (int j = 0; j < 4; j++)
            #pragma unroll
            for (int q = 0; q < 4; q++) acc[i][j][q] = 0.f;

    const uint32_t s0 = (uint32_t)__cvta_generic_to_shared(smem);

    // global->smem: per operand-stage 128 rows x 64B = 512 x 16B; 2 per thread
    const int row0 = tid >> 2, seg0 = (tid & 3) * 16;           // byte seg
    const int row1 = (tid + 256) >> 2, seg1 = ((tid + 256) & 3) * 16;
    const size_t aG0 = ((size_t)r * BB + (size_t)mt * 128 + row0) * CC + seg0;
    const size_t aG1 = ((size_t)r * BB + (size_t)mt * 128 + row1) * CC + seg1;
    const size_t bG0 = ((size_t)r * DD + (size_t)nt * 128 + row0) * CC + seg0;
    const size_t bG1 = ((size_t)r * DD + (size_t)nt * 128 + row1) * CC + seg1;
    const uint32_t d0b = (uint32_t)(row0 * SSTB + seg0);
    const uint32_t d1b = (uint32_t)(row1 * SSTB + seg1);

    auto prefetch = [&](int kt) {
        int stg = kt % NSTG;
        uint32_t aBase = s0 + stg * (2 * STG_BYTES);
        uint32_t bBase = aBase + STG_BYTES;
        size_t ko = (size_t)kt * 64;
        cp16(aBase + d0b, Ap + aG0 + ko);
        cp16(aBase + d1b, Ap + aG1 + ko);
        cp16(bBase + d0b, Bp + bG0 + ko);
        cp16(bBase + d1b, Bp + bG1 + ko);
    };

    // ldmatrix lane offsets (bytes within operand-stage)
    const uint32_t aF = (uint32_t)((wm * 64 + (lane & 15)) * SSTB + (lane >> 4) * 16);
    const uint32_t bRow = (lane & 7) + ((lane & 16) >> 1);
    const uint32_t bSeg = ((lane >> 3) & 1) * 16;
    const uint32_t bF = (uint32_t)((wn * 32 + bRow) * SSTB + bSeg);

    #pragma unroll
    for (int p = 0; p < NSTG - 1; p++) {
        prefetch(p);
        asm volatile("cp.async.commit_group;" ::: "memory");
    }

    const int NKT = CC / 64;   // 16
    for (int kt = 0; kt < NKT; kt++) {
        asm volatile("cp.async.wait_group %0;" :: "n"(NSTG - 2) : "memory");
        __syncthreads();
        if (kt + NSTG - 1 < NKT) prefetch(kt + NSTG - 1);
        asm volatile("cp.async.commit_group;" ::: "memory");

        int stg = kt % NSTG;
        const uint32_t baseA = s0 + stg * (2 * STG_BYTES) + aF;
        const uint32_t baseB = s0 + stg * (2 * STG_BYTES) + STG_BYTES + bF;
        #pragma unroll
        for (int ks = 0; ks < 2; ks++) {          // two k32 steps per 64B row
            const int ko = ks * 32;               // byte offset
            uint32_t afr[4][4], bq[2][4];
            #pragma unroll
            for (int mi = 0; mi < 4; mi++) ldsm4(afr[mi], baseA + mi * 16 * SSTB + ko);
            #pragma unroll
            for (int nb = 0; nb < 2; nb++) ldsm4(bq[nb], baseB + nb * 16 * SSTB + ko);
            #pragma unroll
            for (int mi = 0; mi < 4; mi++)
                #pragma unroll
                for (int nb = 0; nb < 2; nb++) {
                    mma_fp8(acc[mi][2 * nb],     afr[mi], bq[nb][0], bq[nb][1]);
                    mma_fp8(acc[mi][2 * nb + 1], afr[mi], bq[nb][2], bq[nb][3]);
                }
        }
    }

    // epilogue: h = acc + encoder_b -> bf16
    const size_t ebBase = (size_t)r * DD;
    #pragma unroll
    for (int mi = 0; mi < 4; mi++) {
        int b0 = mt * 128 + wm * 64 + mi * 16 + g;
        #pragma unroll
        for (int ni = 0; ni < 4; ni++) {
            int dd0 = nt * 128 + wn * 32 + ni * 8 + 2 * t;
            float e0 = eb[ebBase + dd0];
            float e1 = eb[ebBase + dd0 + 1];
            __nv_bfloat162 v0, v1;
            v0.x = __float2bfloat16(acc[mi][ni][0] + e0);
            v0.y = __float2bfloat16(acc[mi][ni][1] + e1);
            v1.x = __float2bfloat16(acc[mi][ni][2] + e0);
            v1.y = __float2bfloat16(acc[mi][ni][3] + e1);
            *(__nv_bfloat162*)&H[((size_t)b0 * RR + r) * DD + dd0]       = v0;
            *(__nv_bfloat162*)&H[((size_t)(b0 + 8) * RR + r) * DD + dd0] = v1;
        }
    }
}

// ---------------- approx top-NCAND: bisection on register-resident u16 keys -----
// block = r*BB + b (r-major: same-r blocks adjacent for downstream L2 reuse)
__global__ __launch_bounds__(256)
void topk_kernel(const __nv_bfloat16* __restrict__ H) {
    __shared__ int s_warp[8];
    __shared__ int s_total;
    __shared__ int s_cnt, s_tiecnt;
    __shared__ int out_idx[NCAND];
    __shared__ int tie_idx[160];

    const int r = blockIdx.x >> 10;
    const int b = blockIdx.x & 1023;
    const size_t row = (size_t)b * RR + r;            // h layout row
    const int tid = threadIdx.x;              // 256 threads
    const int wid = tid >> 5, lane = tid & 31;
    const uint4* h4 = (const uint4*)(H + row * DD);

    // load 64 bf16 per thread; convert to sortable u16, packed 2-per-u32
    uint32_t kreg[32];
    #pragma unroll
    for (int c = 0; c < 8; c++) {
        uint4 v = h4[tid + c * 256];
        uint32_t w[4] = {v.x, v.y, v.z, v.w};
        #pragma unroll
        for (int q = 0; q < 4; q++) {
            uint32_t x = w[q];
            uint32_t neg = (x >> 15) & 0x00010001u;
            kreg[c * 4 + q] = x ^ (0x80008000u | (neg * 0x7FFFu));
        }
    }

    // bisection: smallest T with #{k > T} < NCAND
    int lo = -1, hi = 65535;
    for (int it = 0; it < 16; it++) {
        int mid = (lo + hi) >> 1;
        uint32_t m2 = (uint32_t)mid * 0x00010001u;
        uint32_t accv = 0;
        #pragma unroll
        for (int i = 0; i < 32; i++) accv += __vsetgtu2(kreg[i], m2);
        int cnt = (int)((accv & 0xFFFF) + (accv >> 16));
        #pragma unroll
        for (int o = 16; o > 0; o >>= 1) cnt += __shfl_xor_sync(0xFFFFFFFFu, cnt, o);
        if (lane == 0) s_warp[wid] = cnt;
        __syncthreads();
        if (tid == 0) {
            int tot = 0;
            #pragma unroll
            for (int w = 0; w < 8; w++) tot += s_warp[w];
            s_total = tot;
        }
        __syncthreads();
        if (s_total < NCAND) hi = mid; else lo = mid;
        __syncthreads();
    }
    const uint32_t T = (uint32_t)hi;

    if (tid == 0) { s_cnt = 0; s_tiecnt = 0; }
    __syncthreads();

    #pragma unroll
    for (int c = 0; c < 8; c++) {
        int ibase = (tid + c * 256) * 8;
        #pragma unroll
        for (int q = 0; q < 4; q++) {
            uint32_t k2 = kreg[c * 4 + q];
            uint32_t klo = k2 & 0xFFFF, khi = k2 >> 16;
            if (klo > T)       { int p = atomicAdd(&s_cnt, 1);    out_idx[p] = ibase + 2 * q; }
            else if (klo == T) { int p = atomicAdd(&s_tiecnt, 1); if (p < 160) tie_idx[p] = ibase + 2 * q; }
            if (khi > T)       { int p = atomicAdd(&s_cnt, 1);    out_idx[p] = ibase + 2 * q + 1; }
            else if (khi == T) { int p = atomicAdd(&s_tiecnt, 1); if (p < 160) tie_idx[p] = ibase + 2 * q + 1; }
        }
    }
    __syncthreads();
    if (tid == 0) {
        int gcnt = s_cnt;
        int need = NCAND - gcnt;
        for (int a = 0; a < need; a++) out_idx[gcnt + a] = tie_idx[a];
    }
    __syncthreads();
    if (tid < NCAND) g_cand[(size_t)blockIdx.x * NCAND + tid] = out_idx[tid];
}

// ---------------- exact fp32 refine of NCAND candidates -> top-32 ---------------
// block = r*BB + b: same-r blocks adjacent -> ew[r] rows (64 MB) L2-resident
__global__ __launch_bounds__(256)
void refine_kernel(const float* __restrict__ ew, const float* __restrict__ eb) {
    __shared__ float sxc[CC];
    __shared__ float sval[NCAND];
    __shared__ int   scand[NCAND];

    const int r = blockIdx.x >> 10;
    const int b = blockIdx.x & 1023;
    const size_t row = (size_t)b * RR + r;            // xc/out row
    const int tid = threadIdx.x;
    const int wid = tid >> 5, lane = tid & 31;

    for (int i = tid; i < CC; i += 256) sxc[i] = g_xc[row * CC + i];
    if (tid < NCAND) scand[tid] = g_cand[(size_t)blockIdx.x * NCAND + tid];
    __syncthreads();

    const float4* xs4 = (const float4*)sxc;
    #pragma unroll
    for (int j = 0; j < NCAND / 8; j++) {
        int ci = j * 8 + wid;                 // 12 rounds x 8 warps = 96
        int d = scand[ci];
        const float4* wr = (const float4*)(ew + ((size_t)r * DD + d) * CC);
        float acc = 0.f;
        #pragma unroll
        for (int it = 0; it < 8; it++) {
            float4 a = xs4[it * 32 + lane];
            float4 bv = wr[it * 32 + lane];
            acc += a.x * bv.x;
            acc += a.y * bv.y;
            acc += a.z * bv.z;
            acc += a.w * bv.w;
        }
        #pragma unroll
        for (int o = 16; o > 0; o >>= 1)
            acc += __shfl_xor_sync(0xFFFFFFFFu, acc, o);
        if (lane == 0) sval[ci] = acc + eb[(size_t)r * DD + d];
    }
    __syncthreads();

    if (tid < NCAND) {
        float v = sval[tid];
        int   d = scand[tid];
        int rank = 0;
        #pragma unroll
        for (int j = 0; j < NCAND; j++) {
            float vj = sval[j];
            int   dj = scand[j];
            rank += (vj > v) || (vj == v && dj < d);
        }
        if (rank < KK) {
            g_idx [row * KK + rank] = d;
            g_vals[row * KK + rank] = v > 0.f ? v : 0.f;
        }
    }
}

// ---------------- sparse decode --------------------------------------------------
__global__ __launch_bounds__(256)
void decode_kernel(const float* __restrict__ db, float* __restrict__ out) {
    __shared__ float sval[KK];
    __shared__ int   sidx[KK];
    const int b = blockIdx.x;
    const int r = blockIdx.y;
    const int tid = threadIdx.x;
    const size_t row = (size_t)b * RR + r;
    if (tid < KK) {
        sval[tid] = g_vals[row * KK + tid];
        sidx[tid] = g_idx [row * KK + tid];
    }
    __syncthreads();
    const float* dwr = g_dwT + (size_t)r * DD * CC;
    #pragma unroll
    for (int it = 0; it < 4; it++) {
        int c = tid + it * 256;
        float acc = db[r * CC + c];
        #pragma unroll
        for (int j = 0; j < KK; j++)
            acc += sval[j] * dwr[(size_t)sidx[j] * CC + c];
        out[row * CC + c] = acc;
    }
}

// ---------------- launch ----------------------------------------------------------
extern "C" void kernel_launch(void* const* d_in, const int* in_sizes, int n_in,
                              void* d_out, int out_size) {
    const float* x  = (const float*)d_in[0];
    const float* ew = (const float*)d_in[1];
    const float* eb = (const float*)d_in[2];
    const float* dw = (const float*)d_in[3];
    const float* db = (const float*)d_in[4];
    float* out = (float*)d_out;

    __nv_bfloat16* h_ptr;  cudaGetSymbolAddress((void**)&h_ptr, g_h);
    uint8_t* a_ptr;        cudaGetSymbolAddress((void**)&a_ptr, g_A8);
    uint8_t* b_ptr;        cudaGetSymbolAddress((void**)&b_ptr, g_B8);

    cudaFuncSetAttribute(encoder_gemm_kernel,
                         cudaFuncAttributeMaxDynamicSharedMemorySize, GEMM_SMEM);

    prep_x_kernel<<<(BB * RR * CC) / 256, 256>>>(x, db);
    prep_w_kernel<<<(RR * DD * CC) / 256, 256>>>(ew);
    transpose_dw_kernel<<<dim3(DD / 32, CC / 32, RR), dim3(32, 8)>>>(dw);
    encoder_gemm_kernel<<<dim3(BB / 128, DD / 128, RR), 256, GEMM_SMEM>>>(a_ptr, b_ptr, eb, h_ptr);
    topk_kernel<<<BB * RR, 256>>>(h_ptr);
    refine_kernel<<<BB * RR, 256>>>(ew, eb);
    decode_kernel<<<dim3(BB, RR), 256>>>(db, out);
}

// round 12
// speedup vs baseline: 1.2953x; 1.2775x over previous
#include <cuda_runtime.h>
#include <cuda_bf16.h>
#include <cuda_fp8.h>
#include <cstdint>

// Problem constants
#define BB 1024
#define RR 8
#define CC 1024
#define DD 16384
#define KK 32
#define NCAND 96
#define SSTB 80         // smem row stride in BYTES (16B-aligned, LDSM conflict-free)
#define NSTG 4          // cp.async pipeline depth
#define STG_BYTES (128 * SSTB)                 // bytes per operand-stage (10240)
#define GEMM_SMEM (NSTG * 2 * STG_BYTES)       // 81920 bytes

// ---------------- device scratch (allocation-free rule: __device__ globals) ----
__device__ __nv_bfloat16 g_h  [(size_t)BB * RR * DD];        // 256 MB approx h (bf16)
__device__ float         g_xc [(size_t)BB * RR * CC];        // 32 MB  x - decoder_b (fp32)
__device__ uint8_t       g_A8 [(size_t)RR * BB * CC];        // 8 MB   e4m3 acts [r][b][c]
__device__ uint8_t       g_B8 [(size_t)RR * DD * CC];        // 128 MB e4m3 weights [r][d][c]
__device__ float         g_dwT[(size_t)RR * DD * CC];        // 512 MB decoder_w transposed

// ---------------- prep ----------------------------------------------------------
__global__ void prep_x_kernel(const float* __restrict__ x,
                              const float* __restrict__ db) {
    int idx = blockIdx.x * blockDim.x + threadIdx.x;
    int b = idx >> 13;
    int r = (idx >> 10) & 7;
    int c = idx & 1023;
    float xc = x[idx] - db[r * CC + c];
    g_xc[idx] = xc;
    g_A8[((size_t)r * BB + b) * CC + c] =
        (uint8_t)__nv_cvt_float_to_fp8(xc, __NV_SATFINITE, __NV_E4M3);
}

__global__ void prep_w_kernel(const float* __restrict__ ew) {
    int idx = blockIdx.x * blockDim.x + threadIdx.x;   // over R*D*C/4
    float4 w4 = ((const float4*)ew)[idx];
    uint32_t p;
    p  = (uint32_t)(uint8_t)__nv_cvt_float_to_fp8(w4.x, __NV_SATFINITE, __NV_E4M3);
    p |= (uint32_t)(uint8_t)__nv_cvt_float_to_fp8(w4.y, __NV_SATFINITE, __NV_E4M3) << 8;
    p |= (uint32_t)(uint8_t)__nv_cvt_float_to_fp8(w4.z, __NV_SATFINITE, __NV_E4M3) << 16;
    p |= (uint32_t)(uint8_t)__nv_cvt_float_to_fp8(w4.w, __NV_SATFINITE, __NV_E4M3) << 24;
    ((uint32_t*)g_B8)[idx] = p;
}

__global__ void transpose_dw_kernel(const float* __restrict__ dw) {
    __shared__ float tile[32][33];
    int d0 = blockIdx.x * 32;
    int c0 = blockIdx.y * 32;
    int r  = blockIdx.z;
    int tx = threadIdx.x, ty = threadIdx.y;
    #pragma unroll
    for (int j = 0; j < 4; j++) {
        int c = c0 + ty + j * 8;
        tile[ty + j * 8][tx] = dw[((size_t)r * CC + c) * DD + d0 + tx];
    }
    __syncthreads();
    #pragma unroll
    for (int j = 0; j < 4; j++) {
        int d = d0 + ty + j * 8;
        g_dwT[((size_t)r * DD + d) * CC + c0 + tx] = tile[tx][ty + j * 8];
    }
}

// ---------------- encoder GEMM: e4m3 mma m16n8k32, 4-stage cp.async + ldmatrix --
// Block 128x128, 8 warps (2x4), warp tile 64x32. Fully-unrolled K loop.

__device__ __forceinline__ void mma_fp8(float* c, const uint32_t* a,
                                        uint32_t b0, uint32_t b1) {
    asm volatile(
        "mma.sync.aligned.m16n8k32.row.col.f32.e4m3.e4m3.f32 "
        "{%0,%1,%2,%3}, {%4,%5,%6,%7}, {%8,%9}, {%0,%1,%2,%3};\n"
        : "+f"(c[0]), "+f"(c[1]), "+f"(c[2]), "+f"(c[3])
        : "r"(a[0]), "r"(a[1]), "r"(a[2]), "r"(a[3]), "r"(b0), "r"(b1));
}

__device__ __forceinline__ void ldsm4(uint32_t* d, uint32_t addr) {
    asm volatile("ldmatrix.sync.aligned.m8n8.x4.shared.b16 {%0,%1,%2,%3}, [%4];"
                 : "=r"(d[0]), "=r"(d[1]), "=r"(d[2]), "=r"(d[3]) : "r"(addr));
}

__device__ __forceinline__ void cp16(uint32_t dst, const void* src) {
    asm volatile("cp.async.cg.shared.global [%0], [%1], 16;\n"
                 :: "r"(dst), "l"(src) : "memory");
}

__global__ __launch_bounds__(256, 2)
void encoder_gemm_kernel(const uint8_t* __restrict__ Ap,
                         const uint8_t* __restrict__ Bp,
                         const float* __restrict__ eb,
                         __nv_bfloat16* __restrict__ H) {
    extern __shared__ uint8_t smem[];   // [NSTG][A|B][128*SSTB]
    const int mt = blockIdx.x;        // 8  (fastest: B-tile L2 reuse)
    const int nt = blockIdx.y;        // 128
    const int r  = blockIdx.z;        // 8
    const int tid = threadIdx.x;
    const int wid = tid >> 5, lane = tid & 31;
    const int wm = wid >> 2, wn = wid & 3;    // 2x4 warps, 64x32 per warp
    const int g = lane >> 2, t = lane & 3;

    float acc[4][4][4];
    #pragma unroll
    for (int i = 0; i < 4; i++)
        #pragma unroll
        for (int j = 0; j < 4; j++)
            #pragma unroll
            for (int q = 0; q < 4; q++) acc[i][j][q] = 0.f;

    const uint32_t s0 = (uint32_t)__cvta_generic_to_shared(smem);

    // global->smem: per operand-stage 128 rows x 64B = 512 x 16B; 2 per thread
    const int row0 = tid >> 2, seg0 = (tid & 3) * 16;           // byte seg
    const int row1 = (tid + 256) >> 2, seg1 = ((tid + 256) & 3) * 16;
    const uint32_t d0b = (uint32_t)(row0 * SSTB + seg0);
    const uint32_t d1b = (uint32_t)(row1 * SSTB + seg1);

    // running global pointers (advance +64 per prefetched chunk)
    const uint8_t* pa0 = Ap + ((size_t)r * BB + (size_t)mt * 128 + row0) * CC + seg0;
    const uint8_t* pa1 = Ap + ((size_t)r * BB + (size_t)mt * 128 + row1) * CC + seg1;
    const uint8_t* pb0 = Bp + ((size_t)r * DD + (size_t)nt * 128 + row0) * CC + seg0;
    const uint8_t* pb1 = Bp + ((size_t)r * DD + (size_t)nt * 128 + row1) * CC + seg1;

    // ldmatrix lane offsets (bytes within operand-stage)
    const uint32_t aF = (uint32_t)((wm * 64 + (lane & 15)) * SSTB + (lane >> 4) * 16);
    const uint32_t bRow = (lane & 7) + ((lane & 16) >> 1);
    const uint32_t bSeg = ((lane >> 3) & 1) * 16;
    const uint32_t bF = (uint32_t)((wn * 32 + bRow) * SSTB + bSeg);

    #pragma unroll
    for (int p = 0; p < NSTG - 1; p++) {
        uint32_t aB = s0 + p * (2 * STG_BYTES);
        cp16(aB + d0b, pa0); cp16(aB + d1b, pa1);
        cp16(aB + STG_BYTES + d0b, pb0); cp16(aB + STG_BYTES + d1b, pb1);
        pa0 += 64; pa1 += 64; pb0 += 64; pb1 += 64;
        asm volatile("cp.async.commit_group;" ::: "memory");
    }

    const int NKT = CC / 64;   // 16
    #pragma unroll
    for (int kt = 0; kt < NKT; kt++) {
        asm volatile("cp.async.wait_group %0;" :: "n"(NSTG - 2) : "memory");
        __syncthreads();
        if (kt + NSTG - 1 < NKT) {
            const uint32_t aB = s0 + ((kt + NSTG - 1) & (NSTG - 1)) * (2 * STG_BYTES);
            cp16(aB + d0b, pa0); cp16(aB + d1b, pa1);
            cp16(aB + STG_BYTES + d0b, pb0); cp16(aB + STG_BYTES + d1b, pb1);
            pa0 += 64; pa1 += 64; pb0 += 64; pb1 += 64;
        }
        asm volatile("cp.async.commit_group;" ::: "memory");

        const uint32_t baseA = s0 + (kt & (NSTG - 1)) * (2 * STG_BYTES) + aF;
        const uint32_t baseB = s0 + (kt & (NSTG - 1)) * (2 * STG_BYTES) + STG_BYTES + bF;
        #pragma unroll
        for (int ks = 0; ks < 2; ks++) {          // two k32 steps per 64B row
            const int ko = ks * 32;               // byte offset
            uint32_t afr[4][4], bq[2][4];
            #pragma unroll
            for (int mi = 0; mi < 4; mi++) ldsm4(afr[mi], baseA + mi * 16 * SSTB + ko);
            #pragma unroll
            for (int nb = 0; nb < 2; nb++) ldsm4(bq[nb], baseB + nb * 16 * SSTB + ko);
            #pragma unroll
            for (int mi = 0; mi < 4; mi++)
                #pragma unroll
                for (int nb = 0; nb < 2; nb++) {
                    mma_fp8(acc[mi][2 * nb],     afr[mi], bq[nb][0], bq[nb][1]);
                    mma_fp8(acc[mi][2 * nb + 1], afr[mi], bq[nb][2], bq[nb][3]);
                }
        }
    }

    // epilogue: h = acc + encoder_b -> bf16
    const size_t ebBase = (size_t)r * DD;
    #pragma unroll
    for (int mi = 0; mi < 4; mi++) {
        int b0 = mt * 128 + wm * 64 + mi * 16 + g;
        #pragma unroll
        for (int ni = 0; ni < 4; ni++) {
            int dd0 = nt * 128 + wn * 32 + ni * 8 + 2 * t;
            float e0 = eb[ebBase + dd0];
            float e1 = eb[ebBase + dd0 + 1];
            __nv_bfloat162 v0, v1;
            v0.x = __float2bfloat16(acc[mi][ni][0] + e0);
            v0.y = __float2bfloat16(acc[mi][ni][1] + e1);
            v1.x = __float2bfloat16(acc[mi][ni][2] + e0);
            v1.y = __float2bfloat16(acc[mi][ni][3] + e1);
            *(__nv_bfloat162*)&H[((size_t)b0 * RR + r) * DD + dd0]       = v0;
            *(__nv_bfloat162*)&H[((size_t)(b0 + 8) * RR + r) * DD + dd0] = v1;
        }
    }
}

// ---------------- fused select (topk->refine) + decode, one block per row -------
// block = r*BB + b (r-major: same-r blocks adjacent -> ew[r]/dwT[r] L2-resident)
__global__ __launch_bounds__(256)
void select_decode_kernel(const __nv_bfloat16* __restrict__ H,
                          const float* __restrict__ ew,
                          const float* __restrict__ eb,
                          const float* __restrict__ db,
                          float* __restrict__ out) {
    __shared__ float sxc[CC];                 // 4 KB xc row
    __shared__ int   s_warp[8];
    __shared__ int   s_total, s_cnt, s_tiecnt;
    __shared__ int   scand[NCAND];
    __shared__ float sval[NCAND];
    __shared__ int   tie_idx[160];
    __shared__ float s_wval[KK];
    __shared__ int   s_widx[KK];

    const int r = blockIdx.x >> 10;
    const int b = blockIdx.x & 1023;
    const size_t row = (size_t)b * RR + r;            // h/xc/out row
    const int tid = threadIdx.x;              // 256 threads
    const int wid = tid >> 5, lane = tid & 31;

    // ---- phase 0: load xc row + h keys ----
    for (int i = tid; i < CC; i += 256) sxc[i] = g_xc[row * CC + i];

    const uint4* h4 = (const uint4*)(H + row * DD);
    uint32_t kreg[32];                        // 64 bf16 per thread, sortable u16 x2
    #pragma unroll
    for (int c = 0; c < 8; c++) {
        uint4 v = h4[tid + c * 256];
        uint32_t w[4] = {v.x, v.y, v.z, v.w};
        #pragma unroll
        for (int q = 0; q < 4; q++) {
            uint32_t x = w[q];
            uint32_t neg = (x >> 15) & 0x00010001u;
            kreg[c * 4 + q] = x ^ (0x80008000u | (neg * 0x7FFFu));
        }
    }

    // ---- phase 1: bisection for NCAND-th key ----
    int lo = -1, hi = 65535;
    for (int it = 0; it < 16; it++) {
        int mid = (lo + hi) >> 1;
        uint32_t m2 = (uint32_t)mid * 0x00010001u;
        uint32_t accv = 0;
        #pragma unroll
        for (int i = 0; i < 32; i++) accv += __vsetgtu2(kreg[i], m2);
        int cnt = (int)((accv & 0xFFFF) + (accv >> 16));
        #pragma unroll
        for (int o = 16; o > 0; o >>= 1) cnt += __shfl_xor_sync(0xFFFFFFFFu, cnt, o);
        if (lane == 0) s_warp[wid] = cnt;
        __syncthreads();
        if (tid == 0) {
            int tot = 0;
            #pragma unroll
            for (int w = 0; w < 8; w++) tot += s_warp[w];
            s_total = tot;
        }
        __syncthreads();
        if (s_total < NCAND) hi = mid; else lo = mid;
        __syncthreads();
    }
    const uint32_t T = (uint32_t)hi;

    if (tid == 0) { s_cnt = 0; s_tiecnt = 0; }
    __syncthreads();

    #pragma unroll
    for (int c = 0; c < 8; c++) {
        int ibase = (tid + c * 256) * 8;
        #pragma unroll
        for (int q = 0; q < 4; q++) {
            uint32_t k2 = kreg[c * 4 + q];
            uint32_t klo = k2 & 0xFFFF, khi = k2 >> 16;
            if (klo > T)       { int p = atomicAdd(&s_cnt, 1);    scand[p] = ibase + 2 * q; }
            else if (klo == T) { int p = atomicAdd(&s_tiecnt, 1); if (p < 160) tie_idx[p] = ibase + 2 * q; }
            if (khi > T)       { int p = atomicAdd(&s_cnt, 1);    scand[p] = ibase + 2 * q + 1; }
            else if (khi == T) { int p = atomicAdd(&s_tiecnt, 1); if (p < 160) tie_idx[p] = ibase + 2 * q + 1; }
        }
    }
    __syncthreads();
    if (tid == 0) {
        int gcnt = s_cnt;
        int need = NCAND - gcnt;              // >= 1
        for (int a = 0; a < need; a++) scand[gcnt + a] = tie_idx[a];
    }
    __syncthreads();

    // ---- phase 2: exact fp32 refine of NCAND candidates ----
    const float4* xs4 = (const float4*)sxc;
    #pragma unroll
    for (int j = 0; j < NCAND / 8; j++) {
        int ci = j * 8 + wid;                 // 12 rounds x 8 warps = 96
        int d = scand[ci];
        const float4* wr = (const float4*)(ew + ((size_t)r * DD + d) * CC);
        float acc = 0.f;
        #pragma unroll
        for (int it = 0; it < 8; it++) {
            float4 a = xs4[it * 32 + lane];
            float4 bv = wr[it * 32 + lane];
            acc += a.x * bv.x;
            acc += a.y * bv.y;
            acc += a.z * bv.z;
            acc += a.w * bv.w;
        }
        #pragma unroll
        for (int o = 16; o > 0; o >>= 1)
            acc += __shfl_xor_sync(0xFFFFFFFFu, acc, o);
        if (lane == 0) sval[ci] = acc + eb[(size_t)r * DD + d];
    }
    __syncthreads();

    // rank top-KK by (value desc, index asc); relu the values
    if (tid < NCAND) {
        float v = sval[tid];
        int   d = scand[tid];
        int rank = 0;
        #pragma unroll
        for (int j = 0; j < NCAND; j++) {
            float vj = sval[j];
            int   dj = scand[j];
            rank += (vj > v) || (vj == v && dj < d);
        }
        if (rank < KK) {
            s_widx[rank] = d;
            s_wval[rank] = v > 0.f ? v : 0.f;
        }
    }
    __syncthreads();

    // ---- phase 3: decode out = db + sum_j val_j * dwT[r][idx_j][:] ----
    const float4* dwr4 = (const float4*)(g_dwT + (size_t)r * DD * CC);
    float4 acc4 = ((const float4*)(db + (size_t)r * CC))[tid];
    #pragma unroll
    for (int j = 0; j < KK; j++) {
        float vj = s_wval[j];
        float4 w4 = dwr4[(size_t)s_widx[j] * (CC / 4) + tid];
        acc4.x += vj * w4.x;
        acc4.y += vj * w4.y;
        acc4.z += vj * w4.z;
        acc4.w += vj * w4.w;
    }
    ((float4*)(out + row * CC))[tid] = acc4;
}

// ---------------- launch ----------------------------------------------------------
extern "C" void kernel_launch(void* const* d_in, const int* in_sizes, int n_in,
                              void* d_out, int out_size) {
    const float* x  = (const float*)d_in[0];
    const float* ew = (const float*)d_in[1];
    const float* eb = (const float*)d_in[2];
    const float* dw = (const float*)d_in[3];
    const float* db = (const float*)d_in[4];
    float* out = (float*)d_out;

    __nv_bfloat16* h_ptr;  cudaGetSymbolAddress((void**)&h_ptr, g_h);
    uint8_t* a_ptr;        cudaGetSymbolAddress((void**)&a_ptr, g_A8);
    uint8_t* b_ptr;        cudaGetSymbolAddress((void**)&b_ptr, g_B8);

    cudaFuncSetAttribute(encoder_gemm_kernel,
                         cudaFuncAttributeMaxDynamicSharedMemorySize, GEMM_SMEM);

    prep_x_kernel<<<(BB * RR * CC) / 256, 256>>>(x, db);
    prep_w_kernel<<<(RR * DD * CC) / 1024, 256>>>(ew);
    transpose_dw_kernel<<<dim3(DD / 32, CC / 32, RR), dim3(32, 8)>>>(dw);
    encoder_gemm_kernel<<<dim3(BB / 128, DD / 128, RR), 256, GEMM_SMEM>>>(a_ptr, b_ptr, eb, h_ptr);
    select_decode_kernel<<<BB * RR, 256>>>(h_ptr, ew, eb, db, out);
}

// round 13
// speedup vs baseline: 1.2956x; 1.0002x over previous
#include <cuda_runtime.h>
#include <cuda_bf16.h>
#include <cuda_fp8.h>
#include <cstdint>

// Problem constants
#define BB 1024
#define RR 8
#define CC 1024
#define DD 16384
#define KK 32
#define NCAND 96
#define SSTB 80         // smem row stride in BYTES (16B-aligned, LDSM conflict-free)
#define NSTG 4          // cp.async pipeline depth
#define STG_BYTES (128 * SSTB)                 // bytes per operand-stage (10240)
#define GEMM_SMEM (NSTG * 2 * STG_BYTES)       // 81920 bytes

// ---------------- device scratch (allocation-free rule: __device__ globals) ----
__device__ __nv_bfloat16 g_h  [(size_t)BB * RR * DD];        // 256 MB approx h (bf16)
__device__ float         g_xc [(size_t)BB * RR * CC];        // 32 MB  x - decoder_b (fp32)
__device__ uint8_t       g_A8 [(size_t)RR * BB * CC];        // 8 MB   e4m3 acts [r][b][c]
__device__ uint8_t       g_B8 [(size_t)RR * DD * CC];        // 128 MB e4m3 weights [r][d][c]
__device__ float         g_dwT[(size_t)RR * DD * CC];        // 512 MB decoder_w transposed

// ---------------- prep ----------------------------------------------------------
__global__ void prep_x_kernel(const float* __restrict__ x,
                              const float* __restrict__ db) {
    int idx = blockIdx.x * blockDim.x + threadIdx.x;
    int b = idx >> 13;
    int r = (idx >> 10) & 7;
    int c = idx & 1023;
    float xc = x[idx] - db[r * CC + c];
    g_xc[idx] = xc;
    g_A8[((size_t)r * BB + b) * CC + c] =
        (uint8_t)__nv_cvt_float_to_fp8(xc, __NV_SATFINITE, __NV_E4M3);
}

__global__ void prep_w_kernel(const float* __restrict__ ew) {
    int idx = blockIdx.x * blockDim.x + threadIdx.x;   // over R*D*C/4
    float4 w4 = ((const float4*)ew)[idx];
    uint32_t p;
    p  = (uint32_t)(uint8_t)__nv_cvt_float_to_fp8(w4.x, __NV_SATFINITE, __NV_E4M3);
    p |= (uint32_t)(uint8_t)__nv_cvt_float_to_fp8(w4.y, __NV_SATFINITE, __NV_E4M3) << 8;
    p |= (uint32_t)(uint8_t)__nv_cvt_float_to_fp8(w4.z, __NV_SATFINITE, __NV_E4M3) << 16;
    p |= (uint32_t)(uint8_t)__nv_cvt_float_to_fp8(w4.w, __NV_SATFINITE, __NV_E4M3) << 24;
    ((uint32_t*)g_B8)[idx] = p;
}

__global__ void transpose_dw_kernel(const float* __restrict__ dw) {
    __shared__ float tile[32][33];
    int d0 = blockIdx.x * 32;
    int c0 = blockIdx.y * 32;
    int r  = blockIdx.z;
    int tx = threadIdx.x, ty = threadIdx.y;
    #pragma unroll
    for (int j = 0; j < 4; j++) {
        int c = c0 + ty + j * 8;
        tile[ty + j * 8][tx] = dw[((size_t)r * CC + c) * DD + d0 + tx];
    }
    __syncthreads();
    #pragma unroll
    for (int j = 0; j < 4; j++) {
        int d = d0 + ty + j * 8;
        g_dwT[((size_t)r * DD + d) * CC + c0 + tx] = tile[tx][ty + j * 8];
    }
}

// ---------------- encoder GEMM: e4m3 mma m16n8k32, 4-stage cp.async + ldmatrix --
// Block 128x128, 8 warps (2x4), warp tile 64x32. Fully-unrolled K loop.

__device__ __forceinline__ void mma_fp8(float* c, const uint32_t* a,
                                        uint32_t b0, uint32_t b1) {
    asm volatile(
        "mma.sync.aligned.m16n8k32.row.col.f32.e4m3.e4m3.f32 "
        "{%0,%1,%2,%3}, {%4,%5,%6,%7}, {%8,%9}, {%0,%1,%2,%3};\n"
        : "+f"(c[0]), "+f"(c[1]), "+f"(c[2]), "+f"(c[3])
        : "r"(a[0]), "r"(a[1]), "r"(a[2]), "r"(a[3]), "r"(b0), "r"(b1));
}

__device__ __forceinline__ void ldsm4(uint32_t* d, uint32_t addr) {
    asm volatile("ldmatrix.sync.aligned.m8n8.x4.shared.b16 {%0,%1,%2,%3}, [%4];"
                 : "=r"(d[0]), "=r"(d[1]), "=r"(d[2]), "=r"(d[3]) : "r"(addr));
}

__device__ __forceinline__ void cp16(uint32_t dst, const void* src) {
    asm volatile("cp.async.cg.shared.global [%0], [%1], 16;\n"
                 :: "r"(dst), "l"(src) : "memory");
}

__global__ __launch_bounds__(256, 2)
void encoder_gemm_kernel(const uint8_t* __restrict__ Ap,
                         const uint8_t* __restrict__ Bp,
                         const float* __restrict__ eb,
                         __nv_bfloat16* __restrict__ H) {
    extern __shared__ uint8_t smem[];   // [NSTG][A|B][128*SSTB]
    const int mt = blockIdx.x;        // 8  (fastest: B-tile L2 reuse)
    const int nt = blockIdx.y;        // 128
    const int r  = blockIdx.z;        // 8
    const int tid = threadIdx.x;
    const int wid = tid >> 5, lane = tid & 31;
    const int wm = wid >> 2, wn = wid & 3;    // 2x4 warps, 64x32 per warp
    const int g = lane >> 2, t = lane & 3;

    float acc[4][4][4];
    #pragma unroll
    for (int i = 0; i < 4; i++)
        #pragma unroll
        for (int j = 0; j < 4; j++)
            #pragma unroll
            for (int q = 0; q < 4; q++) acc[i][j][q] = 0.f;

    const uint32_t s0 = (uint32_t)__cvta_generic_to_shared(smem);

    // global->smem: per operand-stage 128 rows x 64B = 512 x 16B; 2 per thread
    const int row0 = tid >> 2, seg0 = (tid & 3) * 16;           // byte seg
    const int row1 = (tid + 256) >> 2, seg1 = ((tid + 256) & 3) * 16;
    const uint32_t d0b = (uint32_t)(row0 * SSTB + seg0);
    const uint32_t d1b = (uint32_t)(row1 * SSTB + seg1);

    // running global pointers (advance +64 per prefetched chunk)
    const uint8_t* pa0 = Ap + ((size_t)r * BB + (size_t)mt * 128 + row0) * CC + seg0;
    const uint8_t* pa1 = Ap + ((size_t)r * BB + (size_t)mt * 128 + row1) * CC + seg1;
    const uint8_t* pb0 = Bp + ((size_t)r * DD + (size_t)nt * 128 + row0) * CC + seg0;
    const uint8_t* pb1 = Bp + ((size_t)r * DD + (size_t)nt * 128 + row1) * CC + seg1;

    // ldmatrix lane offsets (bytes within operand-stage)
    const uint32_t aF = (uint32_t)((wm * 64 + (lane & 15)) * SSTB + (lane >> 4) * 16);
    const uint32_t bRow = (lane & 7) + ((lane & 16) >> 1);
    const uint32_t bSeg = ((lane >> 3) & 1) * 16;
    const uint32_t bF = (uint32_t)((wn * 32 + bRow) * SSTB + bSeg);

    #pragma unroll
    for (int p = 0; p < NSTG - 1; p++) {
        uint32_t aB = s0 + p * (2 * STG_BYTES);
        cp16(aB + d0b, pa0); cp16(aB + d1b, pa1);
        cp16(aB + STG_BYTES + d0b, pb0); cp16(aB + STG_BYTES + d1b, pb1);
        pa0 += 64; pa1 += 64; pb0 += 64; pb1 += 64;
        asm volatile("cp.async.commit_group;" ::: "memory");
    }

    const int NKT = CC / 64;   // 16
    #pragma unroll
    for (int kt = 0; kt < NKT; kt++) {
        asm volatile("cp.async.wait_group %0;" :: "n"(NSTG - 2) : "memory");
        __syncthreads();
        if (kt + NSTG - 1 < NKT) {
            const uint32_t aB = s0 + ((kt + NSTG - 1) & (NSTG - 1)) * (2 * STG_BYTES);
            cp16(aB + d0b, pa0); cp16(aB + d1b, pa1);
            cp16(aB + STG_BYTES + d0b, pb0); cp16(aB + STG_BYTES + d1b, pb1);
            pa0 += 64; pa1 += 64; pb0 += 64; pb1 += 64;
        }
        asm volatile("cp.async.commit_group;" ::: "memory");

        const uint32_t baseA = s0 + (kt & (NSTG - 1)) * (2 * STG_BYTES) + aF;
        const uint32_t baseB = s0 + (kt & (NSTG - 1)) * (2 * STG_BYTES) + STG_BYTES + bF;
        #pragma unroll
        for (int ks = 0; ks < 2; ks++) {          // two k32 steps per 64B row
            const int ko = ks * 32;               // byte offset
            uint32_t afr[4][4], bq[2][4];
            #pragma unroll
            for (int mi = 0; mi < 4; mi++) ldsm4(afr[mi], baseA + mi * 16 * SSTB + ko);
            #pragma unroll
            for (int nb = 0; nb < 2; nb++) ldsm4(bq[nb], baseB + nb * 16 * SSTB + ko);
            #pragma unroll
            for (int mi = 0; mi < 4; mi++)
                #pragma unroll
                for (int nb = 0; nb < 2; nb++) {
                    mma_fp8(acc[mi][2 * nb],     afr[mi], bq[nb][0], bq[nb][1]);
                    mma_fp8(acc[mi][2 * nb + 1], afr[mi], bq[nb][2], bq[nb][3]);
                }
        }
    }

    // epilogue: h = acc + encoder_b -> bf16
    const size_t ebBase = (size_t)r * DD;
    #pragma unroll
    for (int mi = 0; mi < 4; mi++) {
        int b0 = mt * 128 + wm * 64 + mi * 16 + g;
        #pragma unroll
        for (int ni = 0; ni < 4; ni++) {
            int dd0 = nt * 128 + wn * 32 + ni * 8 + 2 * t;
            float e0 = eb[ebBase + dd0];
            float e1 = eb[ebBase + dd0 + 1];
            __nv_bfloat162 v0, v1;
            v0.x = __float2bfloat16(acc[mi][ni][0] + e0);
            v0.y = __float2bfloat16(acc[mi][ni][1] + e1);
            v1.x = __float2bfloat16(acc[mi][ni][2] + e0);
            v1.y = __float2bfloat16(acc[mi][ni][3] + e1);
            *(__nv_bfloat162*)&H[((size_t)b0 * RR + r) * DD + dd0]       = v0;
            *(__nv_bfloat162*)&H[((size_t)(b0 + 8) * RR + r) * DD + dd0] = v1;
        }
    }
}

// ---------------- fused select (topk->refine) + decode, one block per row -------
// block = r*BB + b (r-major: same-r blocks adjacent -> ew[r]/dwT[r] L2-resident)
__global__ __launch_bounds__(256)
void select_decode_kernel(const __nv_bfloat16* __restrict__ H,
                          const float* __restrict__ ew,
                          const float* __restrict__ eb,
                          const float* __restrict__ db,
                          float* __restrict__ out) {
    __shared__ float sxc[CC];                 // 4 KB xc row
    __shared__ int   s_warp[8];
    __shared__ int   s_total, s_cnt, s_tiecnt;
    __shared__ int   scand[NCAND];
    __shared__ float sval[NCAND];
    __shared__ int   tie_idx[160];
    __shared__ float s_wval[KK];
    __shared__ int   s_widx[KK];

    const int r = blockIdx.x >> 10;
    const int b = blockIdx.x & 1023;
    const size_t row = (size_t)b * RR + r;            // h/xc/out row
    const int tid = threadIdx.x;              // 256 threads
    const int wid = tid >> 5, lane = tid & 31;

    // ---- phase 0: load xc row + h keys ----
    for (int i = tid; i < CC; i += 256) sxc[i] = g_xc[row * CC + i];

    const uint4* h4 = (const uint4*)(H + row * DD);
    uint32_t kreg[32];                        // 64 bf16 per thread, sortable u16 x2
    #pragma unroll
    for (int c = 0; c < 8; c++) {
        uint4 v = h4[tid + c * 256];
        uint32_t w[4] = {v.x, v.y, v.z, v.w};
        #pragma unroll
        for (int q = 0; q < 4; q++) {
            uint32_t x = w[q];
            uint32_t neg = (x >> 15) & 0x00010001u;
            kreg[c * 4 + q] = x ^ (0x80008000u | (neg * 0x7FFFu));
        }
    }

    // ---- phase 1: bisection for NCAND-th key ----
    int lo = -1, hi = 65535;
    for (int it = 0; it < 16; it++) {
        int mid = (lo + hi) >> 1;
        uint32_t m2 = (uint32_t)mid * 0x00010001u;
        uint32_t accv = 0;
        #pragma unroll
        for (int i = 0; i < 32; i++) accv += __vsetgtu2(kreg[i], m2);
        int cnt = (int)((accv & 0xFFFF) + (accv >> 16));
        #pragma unroll
        for (int o = 16; o > 0; o >>= 1) cnt += __shfl_xor_sync(0xFFFFFFFFu, cnt, o);
        if (lane == 0) s_warp[wid] = cnt;
        __syncthreads();
        if (tid == 0) {
            int tot = 0;
            #pragma unroll
            for (int w = 0; w < 8; w++) tot += s_warp[w];
            s_total = tot;
        }
        __syncthreads();
        if (s_total < NCAND) hi = mid; else lo = mid;
        __syncthreads();
    }
    const uint32_t T = (uint32_t)hi;

    if (tid == 0) { s_cnt = 0; s_tiecnt = 0; }
    __syncthreads();

    #pragma unroll
    for (int c = 0; c < 8; c++) {
        int ibase = (tid + c * 256) * 8;
        #pragma unroll
        for (int q = 0; q < 4; q++) {
            uint32_t k2 = kreg[c * 4 + q];
            uint32_t klo = k2 & 0xFFFF, khi = k2 >> 16;
            if (klo > T)       { int p = atomicAdd(&s_cnt, 1);    scand[p] = ibase + 2 * q; }
            else if (klo == T) { int p = atomicAdd(&s_tiecnt, 1); if (p < 160) tie_idx[p] = ibase + 2 * q; }
            if (khi > T)       { int p = atomicAdd(&s_cnt, 1);    scand[p] = ibase + 2 * q + 1; }
            else if (khi == T) { int p = atomicAdd(&s_tiecnt, 1); if (p < 160) tie_idx[p] = ibase + 2 * q + 1; }
        }
    }
    __syncthreads();
    if (tid == 0) {
        int gcnt = s_cnt;
        int need = NCAND - gcnt;              // >= 1
        for (int a = 0; a < need; a++) scand[gcnt + a] = tie_idx[a];
    }
    __syncthreads();

    // ---- phase 2: exact fp32 refine of NCAND candidates ----
    const float4* xs4 = (const float4*)sxc;
    #pragma unroll
    for (int j = 0; j < NCAND / 8; j++) {
        int ci = j * 8 + wid;                 // 12 rounds x 8 warps = 96
        int d = scand[ci];
        const float4* wr = (const float4*)(ew + ((size_t)r * DD + d) * CC);
        float acc = 0.f;
        #pragma unroll
        for (int it = 0; it < 8; it++) {
            float4 a = xs4[it * 32 + lane];
            float4 bv = wr[it * 32 + lane];
            acc += a.x * bv.x;
            acc += a.y * bv.y;
            acc += a.z * bv.z;
            acc += a.w * bv.w;
        }
        #pragma unroll
        for (int o = 16; o > 0; o >>= 1)
            acc += __shfl_xor_sync(0xFFFFFFFFu, acc, o);
        if (lane == 0) sval[ci] = acc + eb[(size_t)r * DD + d];
    }
    __syncthreads();

    // rank top-KK by (value desc, index asc); relu the values
    if (tid < NCAND) {
        float v = sval[tid];
        int   d = scand[tid];
        int rank = 0;
        #pragma unroll
        for (int j = 0; j < NCAND; j++) {
            float vj = sval[j];
            int   dj = scand[j];
            rank += (vj > v) || (vj == v && dj < d);
        }
        if (rank < KK) {
            s_widx[rank] = d;
            s_wval[rank] = v > 0.f ? v : 0.f;
        }
    }
    __syncthreads();

    // ---- phase 3: decode out = db + sum_j val_j * dwT[r][idx_j][:] ----
    const float4* dwr4 = (const float4*)(g_dwT + (size_t)r * DD * CC);
    float4 acc4 = ((const float4*)(db + (size_t)r * CC))[tid];
    #pragma unroll
    for (int j = 0; j < KK; j++) {
        float vj = s_wval[j];
        float4 w4 = dwr4[(size_t)s_widx[j] * (CC / 4) + tid];
        acc4.x += vj * w4.x;
        acc4.y += vj * w4.y;
        acc4.z += vj * w4.z;
        acc4.w += vj * w4.w;
    }
    ((float4*)(out + row * CC))[tid] = acc4;
}

// ---------------- launch ----------------------------------------------------------
extern "C" void kernel_launch(void* const* d_in, const int* in_sizes, int n_in,
                              void* d_out, int out_size) {
    const float* x  = (const float*)d_in[0];
    const float* ew = (const float*)d_in[1];
    const float* eb = (const float*)d_in[2];
    const float* dw = (const float*)d_in[3];
    const float* db = (const float*)d_in[4];
    float* out = (float*)d_out;

    __nv_bfloat16* h_ptr;  cudaGetSymbolAddress((void**)&h_ptr, g_h);
    uint8_t* a_ptr;        cudaGetSymbolAddress((void**)&a_ptr, g_A8);
    uint8_t* b_ptr;        cudaGetSymbolAddress((void**)&b_ptr, g_B8);

    cudaFuncSetAttribute(encoder_gemm_kernel,
                         cudaFuncAttributeMaxDynamicSharedMemorySize, GEMM_SMEM);

    prep_x_kernel<<<(BB * RR * CC) / 256, 256>>>(x, db);
    prep_w_kernel<<<(RR * DD * CC) / 1024, 256>>>(ew);
    transpose_dw_kernel<<<dim3(DD / 32, CC / 32, RR), dim3(32, 8)>>>(dw);
    encoder_gemm_kernel<<<dim3(BB / 128, DD / 128, RR), 256, GEMM_SMEM>>>(a_ptr, b_ptr, eb, h_ptr);
    select_decode_kernel<<<BB * RR, 256>>>(h_ptr, ew, eb, db, out);
}